// round 5
// baseline (speedup 1.0000x reference)
#include <cuda_runtime.h>
#include <cuda_bf16.h>
#include <cstdint>

// Problem dims (fixed)
#define B 64
#define S 2048
#define I 256
#define H 256
#define O 256
#define IH 512
#define G3 768
#define NROWS (B*S)

typedef unsigned long long ull;
typedef ulonglong2 u2;

#define FMA2(acc, a, b) asm("fma.rn.f32x2 %0, %1, %2, %0;" : "+l"(acc) : "l"(a), "l"(b))
#define DUP2(d, s)      asm("mov.b64 %0, {%1, %1};" : "=l"(d) : "f"(s))
#define UNPK2(lo, hi, a) asm("mov.b64 {%0, %1}, %2;" : "=f"(lo), "=f"(hi) : "l"(a))
#define MAPA(out, addr, rank) asm("mapa.shared::cluster.u32 %0, %1, %2;" : "=r"(out) : "r"(addr), "r"(rank))

// ---------------- scratch ----------------------------------------------------
__device__ float g_gx[(size_t)B * S * G3];
__device__ float g_hs[(size_t)B * S * H];
__device__ float g_Wx[G3 * I];
__device__ float g_bx[G3];

// ---------------- weight pack ------------------------------------------------
__global__ void pack_weights(const float* __restrict__ Wr, const float* __restrict__ Wz,
                             const float* __restrict__ Wh, const float* __restrict__ br,
                             const float* __restrict__ bz, const float* __restrict__ bh)
{
    int m = blockIdx.x;
    int d = m & 255;
    const float* Wsrc = (m < 256) ? Wr : (m < 512 ? Wz : Wh);
    for (int k = threadIdx.x; k < I; k += blockDim.x)
        g_Wx[m * I + k] = Wsrc[(size_t)d * IH + k];
    if (threadIdx.x == 0)
        g_bx[m] = (m < 256 ? br : (m < 512 ? bz : bh))[d];
}

// ---------------- tiled GEMM: C = A @ W^T + bias, K=256 ----------------------
__global__ void __launch_bounds__(256)
gemm_bias(const float* __restrict__ A, const float* __restrict__ W,
          const float* __restrict__ bias, float* __restrict__ C, int M)
{
    __shared__ float As[16][128];
    __shared__ float Bs[16][68];

    const int n0 = blockIdx.x * 128;
    const int m0 = blockIdx.y * 64;
    const int t  = threadIdx.x;
    const int tx = t & 15;
    const int ty = t >> 4;

    ull acc[4][4];
#pragma unroll
    for (int i = 0; i < 4; i++)
#pragma unroll
        for (int j = 0; j < 4; j++) acc[i][j] = 0ull;

    for (int k0 = 0; k0 < 256; k0 += 16) {
#pragma unroll
        for (int i = 0; i < 2; i++) {
            int idx = t + i * 256;
            int r = idx & 127, kg = idx >> 7;
            float4 v = *(const float4*)(A + (size_t)(n0 + r) * 256 + k0 + kg * 4);
            As[kg * 4 + 0][r] = v.x;
            As[kg * 4 + 1][r] = v.y;
            As[kg * 4 + 2][r] = v.z;
            As[kg * 4 + 3][r] = v.w;
        }
        {
            int r = t & 63, kg = t >> 6;
            float4 v = *(const float4*)(W + (size_t)(m0 + r) * 256 + k0 + kg * 4);
            Bs[kg * 4 + 0][r] = v.x;
            Bs[kg * 4 + 1][r] = v.y;
            Bs[kg * 4 + 2][r] = v.z;
            Bs[kg * 4 + 3][r] = v.w;
        }
        __syncthreads();
#pragma unroll
        for (int kk = 0; kk < 16; kk++) {
            const u2* ap = (const u2*)&As[kk][ty * 8];
            u2 aA = ap[0];
            u2 aB = ap[1];
            float4 bv = *(const float4*)&Bs[kk][tx * 4];
            ull b0, b1, b2, b3;
            DUP2(b0, bv.x); DUP2(b1, bv.y); DUP2(b2, bv.z); DUP2(b3, bv.w);
            FMA2(acc[0][0], aA.x, b0); FMA2(acc[0][1], aA.x, b1);
            FMA2(acc[0][2], aA.x, b2); FMA2(acc[0][3], aA.x, b3);
            FMA2(acc[1][0], aA.y, b0); FMA2(acc[1][1], aA.y, b1);
            FMA2(acc[1][2], aA.y, b2); FMA2(acc[1][3], aA.y, b3);
            FMA2(acc[2][0], aB.x, b0); FMA2(acc[2][1], aB.x, b1);
            FMA2(acc[2][2], aB.x, b2); FMA2(acc[2][3], aB.x, b3);
            FMA2(acc[3][0], aB.y, b0); FMA2(acc[3][1], aB.y, b1);
            FMA2(acc[3][2], aB.y, b2); FMA2(acc[3][3], aB.y, b3);
        }
        __syncthreads();
    }

    float b0 = bias[m0 + tx * 4 + 0];
    float b1 = bias[m0 + tx * 4 + 1];
    float b2 = bias[m0 + tx * 4 + 2];
    float b3 = bias[m0 + tx * 4 + 3];
#pragma unroll
    for (int ip = 0; ip < 4; ip++) {
        float l0, h0, l1, h1, l2, h2, l3, h3;
        UNPK2(l0, h0, acc[ip][0]); UNPK2(l1, h1, acc[ip][1]);
        UNPK2(l2, h2, acc[ip][2]); UNPK2(l3, h3, acc[ip][3]);
        int r = n0 + ty * 8 + ip * 2;
        float4 o0, o1;
        o0.x = l0 + b0; o0.y = l1 + b1; o0.z = l2 + b2; o0.w = l3 + b3;
        o1.x = h0 + b0; o1.y = h1 + b1; o1.z = h2 + b2; o1.w = h3 + b3;
        *(float4*)(C + (size_t)r * M + m0 + tx * 4)       = o0;
        *(float4*)(C + (size_t)(r + 1) * M + m0 + tx * 4) = o1;
    }
}

// profiler-slot alignment dummy
__global__ void dummy_k() {}

// ---------------- recurrent kernel -------------------------------------------
// 16 clusters x 8 CTAs. Cluster c: batches [4c,4c+4). Rank j: dims [32j,32j+32).
// 384 threads:
//   t in [0,256)   : sub-A (e = t&7 = k-eighth/source rank, dd = t>>3). Wr+Wz regs.
//   t in [256,384) : sub-B (q = t&3 = k-quarter, dd). Wh regs.
// Exchange: plain relaxed remote scalar stores + per-source monotonic flag words
// (fence.acq_rel.cluster + relaxed flag store; consumers spin on local ld.acquire).
// NO mbarriers, NO async proxy, NO cluster barriers inside the loop.
#define RB 148             // floats per source-rank block (4*36 + 4 pad; bank-clean)
#define HB 1184            // 8*RB floats per h parity

__device__ __forceinline__ void cluster_sync_all()
{
    asm volatile("barrier.cluster.arrive.aligned;" ::: "memory");
    asm volatile("barrier.cluster.wait.aligned;" ::: "memory");
}
__device__ __forceinline__ unsigned ld_acq_u32(unsigned a)
{
    unsigned v;
    asm volatile("ld.acquire.cluster.shared::cta.u32 %0, [%1];" : "=r"(v) : "r"(a) : "memory");
    return v;
}
__device__ __forceinline__ void st_remote_f32(unsigned a, float v)
{
    asm volatile("st.relaxed.cluster.shared::cluster.f32 [%0], %1;" :: "r"(a), "f"(v) : "memory");
}
__device__ __forceinline__ void st_remote_u32(unsigned a, unsigned v)
{
    asm volatile("st.relaxed.cluster.shared::cluster.u32 [%0], %1;" :: "r"(a), "r"(v) : "memory");
}
__device__ __forceinline__ void fence_cluster()
{
    asm volatile("fence.acq_rel.cluster;" ::: "memory");
}
__device__ __forceinline__ void spin_ge(unsigned addr, unsigned target)
{
    while (ld_acq_u32(addr) < target) { }
}

extern "C" __global__ void __cluster_dims__(8, 1, 1) __launch_bounds__(384, 1)
gru_rec(const float* __restrict__ gx, const float* __restrict__ Wr,
        const float* __restrict__ Wz, const float* __restrict__ Wh,
        float* __restrict__ hs, float* __restrict__ hlast)
{
    __shared__ __align__(16) float hbuf[2 * HB];   // [parity][src rank][batch][36]
    __shared__ __align__(16) float rhbuf[HB];      // [src rank][batch][36]
    __shared__ float zbuf[128];                    // [dd][batch]
    __shared__ unsigned flag_h[8];                 // per-source h flags (monotonic)
    __shared__ unsigned flag_rh[8];                // per-source rh flags

    const int t  = threadIdx.x;
    const int cl = blockIdx.x >> 3;
    const int j  = blockIdx.x & 7;
    const bool isA = (t < 256);

    const int e  = t & 7;
    const int qh = t & 3;
    const int dd = isA ? (t >> 3) : ((t >> 2) & 31);
    const int dimg = j * 32 + dd;

    // ---- weights into registers
    ull w[32];
    if (isA) {
        const float* rr = Wr + (size_t)dimg * IH + 256 + e * 32;
        const float* rz = Wz + (size_t)dimg * IH + 256 + e * 32;
#pragma unroll
        for (int i = 0; i < 8; i++) {
            u2 v = *(const u2*)(rr + i * 4);
            w[2 * i] = v.x; w[2 * i + 1] = v.y;
            u2 u = *(const u2*)(rz + i * 4);
            w[16 + 2 * i] = u.x; w[17 + 2 * i] = u.y;
        }
    } else {
        const float* rw = Wh + (size_t)dimg * IH + 256 + qh * 64;
#pragma unroll
        for (int i = 0; i < 16; i++) {
            u2 v = *(const u2*)(rw + i * 4);
            w[2 * i] = v.x; w[2 * i + 1] = v.y;
        }
    }

    // ---- init
    for (int i = t; i < 2 * HB; i += 384) hbuf[i] = 0.f;
    for (int i = t; i < HB; i += 384) rhbuf[i] = 0.f;
    if (t < 128) zbuf[t] = 0.f;
    if (t < 8) { flag_h[t] = 0u; flag_rh[t] = 0u; }
    __syncthreads();
    cluster_sync_all();      // zero state visible cluster-wide before any remote store

    // ---- precompute remote addresses
    unsigned rh_dst[8];      // A (e<4): my rh slot in each rank's rhbuf
    unsigned h_dst[8];       // B: my h slot (parity 0) in each rank's hbuf
    if (isA) {
        unsigned l = (unsigned)__cvta_generic_to_shared(&rhbuf[j * RB + (e & 3) * 36 + dd]);
#pragma unroll
        for (int r = 0; r < 8; r++) MAPA(rh_dst[r], l, r);
    } else {
        unsigned l = (unsigned)__cvta_generic_to_shared(&hbuf[j * RB + qh * 36 + dd]);
#pragma unroll
        for (int r = 0; r < 8; r++) MAPA(h_dst[r], l, r);
    }
    unsigned my_flag = 0;    // remote flag word this thread publishes (t<8 / 256<=t<264)
    if (t < 8) {
        unsigned l = (unsigned)__cvta_generic_to_shared(&flag_rh[j]);
        MAPA(my_flag, l, t);
    } else if (t >= 256 && t < 264) {
        unsigned l = (unsigned)__cvta_generic_to_shared(&flag_h[j]);
        MAPA(my_flag, l, t - 256);
    }
    const unsigned pollA = (unsigned)__cvta_generic_to_shared(&flag_h[t & 7]);
    const unsigned pollB = (unsigned)__cvta_generic_to_shared(&flag_rh[t & 7]);

    // ---- gx prefetch (depth 2), one float per thread per step
    const int mybatch = isA ? (e & 3) : qh;
    const int myoff   = isA ? (((e < 4) ? 0 : 256) + dimg) : (512 + dimg);
    const float* gptr = gx + ((size_t)(cl * 4 + mybatch) * S) * G3 + myoff;
    float gv0 = __ldg(gptr);
    float gv1 = __ldg(gptr + G3);

    for (int s = 0; s < S; s++) {
        const int cur = s & 1;
        const int nxt = cur ^ 1;

        float gv = gv0;
        gv0 = gv1;
        if (s + 2 < S) gv1 = __ldg(gptr + 2 * G3);
        gptr += G3;

        if (isA) {
            // ---- wait h(s-1) from all sources (lane polls one flag each)
            spin_ge(pollA, (unsigned)s);
            __syncwarp();

            const float* hbp = hbuf + cur * HB + e * RB;
            // ---- r-gate dot
            float tot_r;
            {
                ull a0 = 0ull, a1 = 0ull, a2 = 0ull, a3 = 0ull;
                const u2* p0 = (const u2*)(hbp + 0 * 36);
                const u2* p1 = (const u2*)(hbp + 1 * 36);
                const u2* p2 = (const u2*)(hbp + 2 * 36);
                const u2* p3 = (const u2*)(hbp + 3 * 36);
#pragma unroll
                for (int i = 0; i < 8; i++) {
                    u2 x0 = p0[i], x1 = p1[i], x2 = p2[i], x3 = p3[i];
                    FMA2(a0, w[2 * i], x0.x); FMA2(a0, w[2 * i + 1], x0.y);
                    FMA2(a1, w[2 * i], x1.x); FMA2(a1, w[2 * i + 1], x1.y);
                    FMA2(a2, w[2 * i], x2.x); FMA2(a2, w[2 * i + 1], x2.y);
                    FMA2(a3, w[2 * i], x3.x); FMA2(a3, w[2 * i + 1], x3.y);
                }
                float lo, hi, p0f, p1f, p2f, p3f;
                UNPK2(lo, hi, a0); p0f = lo + hi;
                UNPK2(lo, hi, a1); p1f = lo + hi;
                UNPK2(lo, hi, a2); p2f = lo + hi;
                UNPK2(lo, hi, a3); p3f = lo + hi;
                p0f += __shfl_xor_sync(0xffffffffu, p0f, 4);
                p1f += __shfl_xor_sync(0xffffffffu, p1f, 4);
                p2f += __shfl_xor_sync(0xffffffffu, p2f, 4);
                p3f += __shfl_xor_sync(0xffffffffu, p3f, 4);
                const int qe = e & 3;
                float u01 = (qe & 1) ? p0f : p1f;
                u01 = __shfl_xor_sync(0xffffffffu, u01, 1);
                float v0 = ((qe & 1) ? p1f : p0f) + u01;
                float u23 = (qe & 1) ? p2f : p3f;
                u23 = __shfl_xor_sync(0xffffffffu, u23, 1);
                float v1 = ((qe & 1) ? p3f : p2f) + u23;
                float uu = (qe & 2) ? v0 : v1;
                uu = __shfl_xor_sync(0xffffffffu, uu, 2);
                tot_r = ((qe & 2) ? v1 : v0) + uu;
            }
            if (e < 4) {
                const int qe = e & 3;
                float gate = __fdividef(1.f, 1.f + __expf(-(tot_r + gv)));
                float hold = hbuf[cur * HB + j * RB + qe * 36 + dd];
                float rh = gate * hold;
#pragma unroll
                for (int r = 0; r < 8; r++) st_remote_f32(rh_dst[r], rh);
            }
            // ---- z-gate dot (overlaps rh fabric flight)
            {
                ull a0 = 0ull, a1 = 0ull, a2 = 0ull, a3 = 0ull;
                const u2* p0 = (const u2*)(hbp + 0 * 36);
                const u2* p1 = (const u2*)(hbp + 1 * 36);
                const u2* p2 = (const u2*)(hbp + 2 * 36);
                const u2* p3 = (const u2*)(hbp + 3 * 36);
#pragma unroll
                for (int i = 0; i < 8; i++) {
                    u2 x0 = p0[i], x1 = p1[i], x2 = p2[i], x3 = p3[i];
                    FMA2(a0, w[16 + 2 * i], x0.x); FMA2(a0, w[17 + 2 * i], x0.y);
                    FMA2(a1, w[16 + 2 * i], x1.x); FMA2(a1, w[17 + 2 * i], x1.y);
                    FMA2(a2, w[16 + 2 * i], x2.x); FMA2(a2, w[17 + 2 * i], x2.y);
                    FMA2(a3, w[16 + 2 * i], x3.x); FMA2(a3, w[17 + 2 * i], x3.y);
                }
                float lo, hi, p0f, p1f, p2f, p3f;
                UNPK2(lo, hi, a0); p0f = lo + hi;
                UNPK2(lo, hi, a1); p1f = lo + hi;
                UNPK2(lo, hi, a2); p2f = lo + hi;
                UNPK2(lo, hi, a3); p3f = lo + hi;
                p0f += __shfl_xor_sync(0xffffffffu, p0f, 4);
                p1f += __shfl_xor_sync(0xffffffffu, p1f, 4);
                p2f += __shfl_xor_sync(0xffffffffu, p2f, 4);
                p3f += __shfl_xor_sync(0xffffffffu, p3f, 4);
                const int qe = e & 3;
                float u01 = (qe & 1) ? p0f : p1f;
                u01 = __shfl_xor_sync(0xffffffffu, u01, 1);
                float v0 = ((qe & 1) ? p1f : p0f) + u01;
                float u23 = (qe & 1) ? p2f : p3f;
                u23 = __shfl_xor_sync(0xffffffffu, u23, 1);
                float v1 = ((qe & 1) ? p3f : p2f) + u23;
                float uu = (qe & 2) ? v0 : v1;
                uu = __shfl_xor_sync(0xffffffffu, uu, 2);
                float tot_z = ((qe & 2) ? v1 : v0) + uu;
                if (e >= 4) {
                    float gate = __fdividef(1.f, 1.f + __expf(-(tot_z + gv)));
                    zbuf[dd * 4 + qe] = gate;
                }
            }
            // ---- publish rh + z: group barrier, then 8 flag stores
            asm volatile("bar.sync 1, 256;" ::: "memory");
            if (t < 8) {
                fence_cluster();
                st_remote_u32(my_flag, (unsigned)(s + 1));
            }
        } else {
            // ---- wait rh(s) from all sources
            spin_ge(pollB, (unsigned)(s + 1));
            __syncwarp();

            ull a0 = 0ull, a1 = 0ull, a2 = 0ull, a3 = 0ull;
            const float* r0 = rhbuf + (2 * qh) * RB;
            const float* r1 = rhbuf + (2 * qh + 1) * RB;
#pragma unroll
            for (int b = 0; b < 4; b++) {
                ull* acc = (b == 0) ? &a0 : (b == 1) ? &a1 : (b == 2) ? &a2 : &a3;
                const u2* pa = (const u2*)(r0 + b * 36);
                const u2* pb = (const u2*)(r1 + b * 36);
#pragma unroll
                for (int i = 0; i < 8; i++) {
                    u2 xa = pa[i];
                    FMA2(*acc, w[2 * i], xa.x); FMA2(*acc, w[2 * i + 1], xa.y);
                }
#pragma unroll
                for (int i = 0; i < 8; i++) {
                    u2 xb = pb[i];
                    FMA2(*acc, w[16 + 2 * i], xb.x); FMA2(*acc, w[17 + 2 * i], xb.y);
                }
            }
            float lo, hi, p0f, p1f, p2f, p3f;
            UNPK2(lo, hi, a0); p0f = lo + hi;
            UNPK2(lo, hi, a1); p1f = lo + hi;
            UNPK2(lo, hi, a2); p2f = lo + hi;
            UNPK2(lo, hi, a3); p3f = lo + hi;
            float u01 = (qh & 1) ? p0f : p1f;
            u01 = __shfl_xor_sync(0xffffffffu, u01, 1);
            float v0 = ((qh & 1) ? p1f : p0f) + u01;
            float u23 = (qh & 1) ? p2f : p3f;
            u23 = __shfl_xor_sync(0xffffffffu, u23, 1);
            float v1 = ((qh & 1) ? p3f : p2f) + u23;
            float uu = (qh & 2) ? v0 : v1;
            uu = __shfl_xor_sync(0xffffffffu, uu, 2);
            float tot = ((qh & 2) ? v1 : v0) + uu;

            float pre2 = tot + gv;
            float e2 = __expf(2.f * pre2);
            float htil = 1.f - __fdividef(2.f, e2 + 1.f);
            float hold = hbuf[cur * HB + j * RB + qh * 36 + dd];
            float z = zbuf[dd * 4 + qh];
            float hn = fmaf(z, htil - hold, hold);

            const unsigned poff = (unsigned)(nxt * (HB * 4));
#pragma unroll
            for (int r = 0; r < 8; r++) st_remote_f32(h_dst[r] + poff, hn);
            hs[((size_t)(cl * 4 + qh) * S + s) * H + dimg] = hn;
            if (s == S - 1) hlast[(size_t)(cl * 4 + qh) * H + dimg] = hn;

            asm volatile("bar.sync 2, 128;" ::: "memory");
            if (t < 264) {
                fence_cluster();
                st_remote_u32(my_flag, (unsigned)(s + 1));
            }
        }
    }

    // ---- drain: all deliveries to THIS CTA have landed once all h flags hit S
    spin_ge(pollA, (unsigned)S);
    cluster_sync_all();
}

// ---------------- launch ------------------------------------------------------
extern "C" void kernel_launch(void* const* d_in, const int* in_sizes, int n_in,
                              void* d_out, int out_size)
{
    const float* x    = (const float*)d_in[0];
    const float* W_r  = (const float*)d_in[1];
    const float* b_r  = (const float*)d_in[2];
    const float* W_z  = (const float*)d_in[3];
    const float* b_z  = (const float*)d_in[4];
    const float* W_h  = (const float*)d_in[5];
    const float* b_h  = (const float*)d_in[6];
    const float* W_fc = (const float*)d_in[7];
    const float* b_fc = (const float*)d_in[8];
    float* out = (float*)d_out;
    float* hlast = out + (size_t)B * S * O;

    float *gx, *hsp, *Wx, *bx;
    cudaGetSymbolAddress((void**)&gx,  g_gx);
    cudaGetSymbolAddress((void**)&hsp, g_hs);
    cudaGetSymbolAddress((void**)&Wx,  g_Wx);
    cudaGetSymbolAddress((void**)&bx,  g_bx);

    pack_weights<<<G3, 64>>>(W_r, W_z, W_h, b_r, b_z, b_h);
    gemm_bias<<<dim3(NROWS / 128, G3 / 64), 256>>>(x, Wx, bx, gx, G3);
    dummy_k<<<1, 32>>>();   // keeps gru_rec on the ncu capture slot
    gru_rec<<<128, 384>>>(gx, W_r, W_z, W_h, hsp, hlast);
    gemm_bias<<<dim3(NROWS / 128, O / 64), 256>>>(hsp, W_fc, b_fc, out, O);
}

// round 7
// speedup vs baseline: 2.4132x; 2.4132x over previous
#include <cuda_runtime.h>
#include <cuda_bf16.h>
#include <cstdint>

// Problem dims (fixed)
#define B 64
#define S 2048
#define I 256
#define H 256
#define O 256
#define IH 512
#define G3 768
#define NROWS (B*S)

typedef unsigned long long ull;
typedef ulonglong2 u2;

#define FMA2(acc, a, b) asm("fma.rn.f32x2 %0, %1, %2, %0;" : "+l"(acc) : "l"(a), "l"(b))
#define DUP2(d, s)      asm("mov.b64 %0, {%1, %1};" : "=l"(d) : "f"(s))
#define UNPK2(lo, hi, a) asm("mov.b64 {%0, %1}, %2;" : "=f"(lo), "=f"(hi) : "l"(a))
#define MAPA(out, addr, rank) asm("mapa.shared::cluster.u32 %0, %1, %2;" : "=r"(out) : "r"(addr), "r"(rank))

// ---------------- scratch ----------------------------------------------------
__device__ float g_gx[(size_t)B * S * G3];
__device__ float g_hs[(size_t)B * S * H];
__device__ float g_Wx[G3 * I];
__device__ float g_bx[G3];

// ---------------- weight pack ------------------------------------------------
__global__ void pack_weights(const float* __restrict__ Wr, const float* __restrict__ Wz,
                             const float* __restrict__ Wh, const float* __restrict__ br,
                             const float* __restrict__ bz, const float* __restrict__ bh)
{
    int m = blockIdx.x;
    int d = m & 255;
    const float* Wsrc = (m < 256) ? Wr : (m < 512 ? Wz : Wh);
    for (int k = threadIdx.x; k < I; k += blockDim.x)
        g_Wx[m * I + k] = Wsrc[(size_t)d * IH + k];
    if (threadIdx.x == 0)
        g_bx[m] = (m < 256 ? br : (m < 512 ? bz : bh))[d];
}

// ---------------- tiled GEMM: C = A @ W^T + bias, K=256 ----------------------
__global__ void __launch_bounds__(256)
gemm_bias(const float* __restrict__ A, const float* __restrict__ W,
          const float* __restrict__ bias, float* __restrict__ C, int M)
{
    __shared__ float As[16][128];
    __shared__ float Bs[16][68];

    const int n0 = blockIdx.x * 128;
    const int m0 = blockIdx.y * 64;
    const int t  = threadIdx.x;
    const int tx = t & 15;
    const int ty = t >> 4;

    ull acc[4][4];
#pragma unroll
    for (int i = 0; i < 4; i++)
#pragma unroll
        for (int j = 0; j < 4; j++) acc[i][j] = 0ull;

    for (int k0 = 0; k0 < 256; k0 += 16) {
#pragma unroll
        for (int i = 0; i < 2; i++) {
            int idx = t + i * 256;
            int r = idx & 127, kg = idx >> 7;
            float4 v = *(const float4*)(A + (size_t)(n0 + r) * 256 + k0 + kg * 4);
            As[kg * 4 + 0][r] = v.x;
            As[kg * 4 + 1][r] = v.y;
            As[kg * 4 + 2][r] = v.z;
            As[kg * 4 + 3][r] = v.w;
        }
        {
            int r = t & 63, kg = t >> 6;
            float4 v = *(const float4*)(W + (size_t)(m0 + r) * 256 + k0 + kg * 4);
            Bs[kg * 4 + 0][r] = v.x;
            Bs[kg * 4 + 1][r] = v.y;
            Bs[kg * 4 + 2][r] = v.z;
            Bs[kg * 4 + 3][r] = v.w;
        }
        __syncthreads();
#pragma unroll
        for (int kk = 0; kk < 16; kk++) {
            const u2* ap = (const u2*)&As[kk][ty * 8];
            u2 aA = ap[0];
            u2 aB = ap[1];
            float4 bv = *(const float4*)&Bs[kk][tx * 4];
            ull b0, b1, b2, b3;
            DUP2(b0, bv.x); DUP2(b1, bv.y); DUP2(b2, bv.z); DUP2(b3, bv.w);
            FMA2(acc[0][0], aA.x, b0); FMA2(acc[0][1], aA.x, b1);
            FMA2(acc[0][2], aA.x, b2); FMA2(acc[0][3], aA.x, b3);
            FMA2(acc[1][0], aA.y, b0); FMA2(acc[1][1], aA.y, b1);
            FMA2(acc[1][2], aA.y, b2); FMA2(acc[1][3], aA.y, b3);
            FMA2(acc[2][0], aB.x, b0); FMA2(acc[2][1], aB.x, b1);
            FMA2(acc[2][2], aB.x, b2); FMA2(acc[2][3], aB.x, b3);
            FMA2(acc[3][0], aB.y, b0); FMA2(acc[3][1], aB.y, b1);
            FMA2(acc[3][2], aB.y, b2); FMA2(acc[3][3], aB.y, b3);
        }
        __syncthreads();
    }

    float b0 = bias[m0 + tx * 4 + 0];
    float b1 = bias[m0 + tx * 4 + 1];
    float b2 = bias[m0 + tx * 4 + 2];
    float b3 = bias[m0 + tx * 4 + 3];
#pragma unroll
    for (int ip = 0; ip < 4; ip++) {
        float l0, h0, l1, h1, l2, h2, l3, h3;
        UNPK2(l0, h0, acc[ip][0]); UNPK2(l1, h1, acc[ip][1]);
        UNPK2(l2, h2, acc[ip][2]); UNPK2(l3, h3, acc[ip][3]);
        int r = n0 + ty * 8 + ip * 2;
        float4 o0, o1;
        o0.x = l0 + b0; o0.y = l1 + b1; o0.z = l2 + b2; o0.w = l3 + b3;
        o1.x = h0 + b0; o1.y = h1 + b1; o1.z = h2 + b2; o1.w = h3 + b3;
        *(float4*)(C + (size_t)r * M + m0 + tx * 4)       = o0;
        *(float4*)(C + (size_t)(r + 1) * M + m0 + tx * 4) = o1;
    }
}

// profiler-slot alignment dummy
__global__ void dummy_k() {}

// ---------------- recurrent kernel -------------------------------------------
// 16 clusters x 8 CTAs. Cluster c: batches [4c,4c+4). Rank j: dims [32j,32j+32).
// 384 threads:
//   t in [0,256)   : sub-A (e = t&7 = k-eighth/source rank, dd = t>>3). Wr+Wz regs.
//                    r and z dots INTERLEAVED over one h-load stream.
//   t in [256,384) : sub-B (qh = t&3 = k-quarter, dd). Wh regs.
// Exchange: plain st.relaxed.cluster remote scalar data stores; signaling via
// remote mbarrier.arrive.release.cluster (count-8 barrier, parity auto-flip).
// NO fences, NO async proxy, NO expect_tx, NO re-arm in the loop.
// R7 fix: final drain waits CONSTANT parity (S-1)&1 (R6 deadlocked: sub-B threads
// waited stale parity 0 = phase 2048, which never completes).
#define RB 148             // floats per source-rank block (4*36 + 4 pad; bank-clean)
#define HB 1184            // 8*RB floats per h parity

__device__ __forceinline__ void cluster_sync_all()
{
    asm volatile("barrier.cluster.arrive.aligned;" ::: "memory");
    asm volatile("barrier.cluster.wait.aligned;" ::: "memory");
}
__device__ __forceinline__ void mbar_init(unsigned bar, unsigned count)
{
    asm volatile("mbarrier.init.shared.b64 [%0], %1;" :: "r"(bar), "r"(count) : "memory");
}
__device__ __forceinline__ void mbar_arrive_remote(unsigned rbar)
{
    asm volatile("mbarrier.arrive.release.cluster.shared::cluster.b64 _, [%0];"
                 :: "r"(rbar) : "memory");
}
__device__ __forceinline__ void mbar_wait_acq(unsigned bar, unsigned phase)
{
    unsigned done;
    asm volatile(
        "{\n\t.reg .pred p;\n\t"
        "mbarrier.try_wait.parity.acquire.cluster.shared::cta.b64 p, [%1], %2;\n\t"
        "selp.b32 %0, 1, 0, p;\n\t}"
        : "=r"(done) : "r"(bar), "r"(phase) : "memory");
    if (!done) {
        asm volatile(
            "{\n\t.reg .pred P1;\n\t"
            "WL_%=:\n\t"
            "mbarrier.try_wait.parity.acquire.cluster.shared::cta.b64 P1, [%0], %1, 0x989680;\n\t"
            "@P1 bra.uni WD_%=;\n\t"
            "bra.uni WL_%=;\n\t"
            "WD_%=:\n\t}"
            :: "r"(bar), "r"(phase) : "memory");
    }
}
__device__ __forceinline__ void st_remote_f32(unsigned a, float v)
{
    asm volatile("st.relaxed.cluster.shared::cluster.f32 [%0], %1;" :: "r"(a), "f"(v) : "memory");
}

extern "C" __global__ void __cluster_dims__(8, 1, 1) __launch_bounds__(384, 1)
gru_rec(const float* __restrict__ gx, const float* __restrict__ Wr,
        const float* __restrict__ Wz, const float* __restrict__ Wh,
        float* __restrict__ hs, float* __restrict__ hlast)
{
    __shared__ __align__(16) float hbuf[2 * HB];   // [parity][src rank][batch][36]
    __shared__ __align__(16) float rhbuf[HB];      // [src rank][batch][36]
    __shared__ float zbuf[128];                    // [dd][batch]
    __shared__ ull mbars[2];                       // [0]=barH, [1]=barRH

    const int t  = threadIdx.x;
    const int cl = blockIdx.x >> 3;
    const int j  = blockIdx.x & 7;
    const bool isA = (t < 256);

    const int e  = t & 7;
    const int qh = t & 3;
    const int dd = isA ? (t >> 3) : ((t >> 2) & 31);
    const int dimg = j * 32 + dd;

    const unsigned barH  = (unsigned)__cvta_generic_to_shared(&mbars[0]);
    const unsigned barRH = (unsigned)__cvta_generic_to_shared(&mbars[1]);

    // ---- weights into registers
    ull w[32];
    if (isA) {
        const float* rr = Wr + (size_t)dimg * IH + 256 + e * 32;
        const float* rz = Wz + (size_t)dimg * IH + 256 + e * 32;
#pragma unroll
        for (int i = 0; i < 8; i++) {
            u2 v = *(const u2*)(rr + i * 4);
            w[2 * i] = v.x; w[2 * i + 1] = v.y;
            u2 u = *(const u2*)(rz + i * 4);
            w[16 + 2 * i] = u.x; w[17 + 2 * i] = u.y;
        }
    } else {
        const float* rw = Wh + (size_t)dimg * IH + 256 + qh * 64;
#pragma unroll
        for (int i = 0; i < 16; i++) {
            u2 v = *(const u2*)(rw + i * 4);
            w[2 * i] = v.x; w[2 * i + 1] = v.y;
        }
    }

    // ---- init
    for (int i = t; i < 2 * HB; i += 384) hbuf[i] = 0.f;
    for (int i = t; i < HB; i += 384) rhbuf[i] = 0.f;
    if (t < 128) zbuf[t] = 0.f;
    if (t == 0) {
        mbar_init(barH, 8);     // 8 arrives (one per source CTA) per phase
        mbar_init(barRH, 8);
    }
    __syncthreads();
    cluster_sync_all();      // zero state + barriers visible before any remote traffic

    // ---- precompute remote addresses
    unsigned rh_dst[8];      // A (e<4): my rh slot in each rank's rhbuf
    unsigned h_dst[8];       // B: my h slot (parity 0) in each rank's hbuf
    if (isA) {
        unsigned l = (unsigned)__cvta_generic_to_shared(&rhbuf[j * RB + (e & 3) * 36 + dd]);
#pragma unroll
        for (int r = 0; r < 8; r++) MAPA(rh_dst[r], l, r);
    } else {
        unsigned l = (unsigned)__cvta_generic_to_shared(&hbuf[j * RB + qh * 36 + dd]);
#pragma unroll
        for (int r = 0; r < 8; r++) MAPA(h_dst[r], l, r);
    }
    unsigned my_arr = 0;     // remote barrier this thread arrives on
    if (t < 8)                      MAPA(my_arr, barRH, t);
    else if (t >= 256 && t < 264)   MAPA(my_arr, barH, t - 256);

    // ---- gx prefetch (depth 2), one float per thread per step
    const int mybatch = isA ? (e & 3) : qh;
    const int myoff   = isA ? (((e < 4) ? 0 : 256) + dimg) : (512 + dimg);
    const float* gptr = gx + ((size_t)(cl * 4 + mybatch) * S) * G3 + myoff;
    float gv0 = __ldg(gptr);
    float gv1 = __ldg(gptr + G3);

    unsigned parH = 0, parRH = 0;

    for (int s = 0; s < S; s++) {
        const int cur = s & 1;
        const int nxt = cur ^ 1;

        float gv = gv0;
        gv0 = gv1;
        if (s + 2 < S) gv1 = __ldg(gptr + 2 * G3);
        gptr += G3;

        if (isA) {
            // ---- wait h(s-1) from all 8 sources
            if (s > 0) { mbar_wait_acq(barH, parH); parH ^= 1; }

            const float* hbp = hbuf + cur * HB + e * RB;
            // ---- r and z dots interleaved over one h stream
            ull r0 = 0ull, r1 = 0ull, r2 = 0ull, r3 = 0ull;
            ull z0 = 0ull, z1 = 0ull, z2 = 0ull, z3 = 0ull;
            {
                const u2* p0 = (const u2*)(hbp + 0 * 36);
                const u2* p1 = (const u2*)(hbp + 1 * 36);
                const u2* p2 = (const u2*)(hbp + 2 * 36);
                const u2* p3 = (const u2*)(hbp + 3 * 36);
#pragma unroll
                for (int i = 0; i < 8; i++) {
                    u2 x0 = p0[i], x1 = p1[i], x2 = p2[i], x3 = p3[i];
                    FMA2(r0, w[2 * i], x0.x); FMA2(r0, w[2 * i + 1], x0.y);
                    FMA2(z0, w[16 + 2 * i], x0.x); FMA2(z0, w[17 + 2 * i], x0.y);
                    FMA2(r1, w[2 * i], x1.x); FMA2(r1, w[2 * i + 1], x1.y);
                    FMA2(z1, w[16 + 2 * i], x1.x); FMA2(z1, w[17 + 2 * i], x1.y);
                    FMA2(r2, w[2 * i], x2.x); FMA2(r2, w[2 * i + 1], x2.y);
                    FMA2(z2, w[16 + 2 * i], x2.x); FMA2(z2, w[17 + 2 * i], x2.y);
                    FMA2(r3, w[2 * i], x3.x); FMA2(r3, w[2 * i + 1], x3.y);
                    FMA2(z3, w[16 + 2 * i], x3.x); FMA2(z3, w[17 + 2 * i], x3.y);
                }
            }
            // ---- unpack + interleaved shfl reductions (r-chain and z-chain overlap)
            float lo, hi;
            float pr0, pr1, pr2, pr3, pz0, pz1, pz2, pz3;
            UNPK2(lo, hi, r0); pr0 = lo + hi;
            UNPK2(lo, hi, z0); pz0 = lo + hi;
            UNPK2(lo, hi, r1); pr1 = lo + hi;
            UNPK2(lo, hi, z1); pz1 = lo + hi;
            UNPK2(lo, hi, r2); pr2 = lo + hi;
            UNPK2(lo, hi, z2); pz2 = lo + hi;
            UNPK2(lo, hi, r3); pr3 = lo + hi;
            UNPK2(lo, hi, z3); pz3 = lo + hi;
            pr0 += __shfl_xor_sync(0xffffffffu, pr0, 4);
            pz0 += __shfl_xor_sync(0xffffffffu, pz0, 4);
            pr1 += __shfl_xor_sync(0xffffffffu, pr1, 4);
            pz1 += __shfl_xor_sync(0xffffffffu, pz1, 4);
            pr2 += __shfl_xor_sync(0xffffffffu, pr2, 4);
            pz2 += __shfl_xor_sync(0xffffffffu, pz2, 4);
            pr3 += __shfl_xor_sync(0xffffffffu, pr3, 4);
            pz3 += __shfl_xor_sync(0xffffffffu, pz3, 4);
            const int qe = e & 3;
            float ur01 = (qe & 1) ? pr0 : pr1;
            float uz01 = (qe & 1) ? pz0 : pz1;
            ur01 = __shfl_xor_sync(0xffffffffu, ur01, 1);
            uz01 = __shfl_xor_sync(0xffffffffu, uz01, 1);
            float vr0 = ((qe & 1) ? pr1 : pr0) + ur01;
            float vz0 = ((qe & 1) ? pz1 : pz0) + uz01;
            float ur23 = (qe & 1) ? pr2 : pr3;
            float uz23 = (qe & 1) ? pz2 : pz3;
            ur23 = __shfl_xor_sync(0xffffffffu, ur23, 1);
            uz23 = __shfl_xor_sync(0xffffffffu, uz23, 1);
            float vr1 = ((qe & 1) ? pr3 : pr2) + ur23;
            float vz1 = ((qe & 1) ? pz3 : pz2) + uz23;
            float wr = (qe & 2) ? vr0 : vr1;
            float wz = (qe & 2) ? vz0 : vz1;
            wr = __shfl_xor_sync(0xffffffffu, wr, 2);
            wz = __shfl_xor_sync(0xffffffffu, wz, 2);
            float tot_r = ((qe & 2) ? vr1 : vr0) + wr;
            float tot_z = ((qe & 2) ? vz1 : vz0) + wz;

            if (e < 4) {
                float gate = __fdividef(1.f, 1.f + __expf(-(tot_r + gv)));
                float hold = hbuf[cur * HB + j * RB + qe * 36 + dd];
                float rh = gate * hold;
#pragma unroll
                for (int r = 0; r < 8; r++) st_remote_f32(rh_dst[r], rh);
            } else {
                float gate = __fdividef(1.f, 1.f + __expf(-(tot_z + gv)));
                zbuf[dd * 4 + qe] = gate;
            }
            // ---- publish rh + z: group barrier, 8 elected release-arrives
            asm volatile("bar.sync 1, 256;" ::: "memory");
            if (t < 8) mbar_arrive_remote(my_arr);
        } else {
            // ---- wait rh(s) from all 8 sources
            mbar_wait_acq(barRH, parRH); parRH ^= 1;

            ull a0 = 0ull, a1 = 0ull, a2 = 0ull, a3 = 0ull;
            const float* rp0 = rhbuf + (2 * qh) * RB;
            const float* rp1 = rhbuf + (2 * qh + 1) * RB;
#define SUBB_BATCH(ACC, BIDX)                                                   \
            {                                                                   \
                const u2* pa = (const u2*)(rp0 + (BIDX) * 36);                  \
                const u2* pb = (const u2*)(rp1 + (BIDX) * 36);                  \
                _Pragma("unroll")                                               \
                for (int i = 0; i < 8; i++) {                                   \
                    u2 xa = pa[i];                                              \
                    FMA2(ACC, w[2 * i], xa.x); FMA2(ACC, w[2 * i + 1], xa.y);   \
                }                                                               \
                _Pragma("unroll")                                               \
                for (int i = 0; i < 8; i++) {                                   \
                    u2 xb = pb[i];                                              \
                    FMA2(ACC, w[16 + 2 * i], xb.x); FMA2(ACC, w[17 + 2 * i], xb.y); \
                }                                                               \
            }
            SUBB_BATCH(a0, 0)
            SUBB_BATCH(a1, 1)
            SUBB_BATCH(a2, 2)
            SUBB_BATCH(a3, 3)
#undef SUBB_BATCH

            float lo, hi, p0f, p1f, p2f, p3f;
            UNPK2(lo, hi, a0); p0f = lo + hi;
            UNPK2(lo, hi, a1); p1f = lo + hi;
            UNPK2(lo, hi, a2); p2f = lo + hi;
            UNPK2(lo, hi, a3); p3f = lo + hi;
            float u01 = (qh & 1) ? p0f : p1f;
            u01 = __shfl_xor_sync(0xffffffffu, u01, 1);
            float v0 = ((qh & 1) ? p1f : p0f) + u01;
            float u23 = (qh & 1) ? p2f : p3f;
            u23 = __shfl_xor_sync(0xffffffffu, u23, 1);
            float v1 = ((qh & 1) ? p3f : p2f) + u23;
            float uu = (qh & 2) ? v0 : v1;
            uu = __shfl_xor_sync(0xffffffffu, uu, 2);
            float tot = ((qh & 2) ? v1 : v0) + uu;

            float pre2 = tot + gv;
            float e2 = __expf(2.f * pre2);
            float htil = 1.f - __fdividef(2.f, e2 + 1.f);
            float hold = hbuf[cur * HB + j * RB + qh * 36 + dd];
            float z = zbuf[dd * 4 + qh];
            float hn = fmaf(z, htil - hold, hold);

            const unsigned poff = (unsigned)(nxt * (HB * 4));
#pragma unroll
            for (int r = 0; r < 8; r++) st_remote_f32(h_dst[r] + poff, hn);
            hs[((size_t)(cl * 4 + qh) * S + s) * H + dimg] = hn;
            if (s == S - 1) hlast[(size_t)(cl * 4 + qh) * H + dimg] = hn;

            asm volatile("bar.sync 2, 128;" ::: "memory");
            if (t >= 256 && t < 264) mbar_arrive_remote(my_arr);
        }
    }

    // ---- drain: wait phase S-1 of barH with CONSTANT parity (R6 bugfix).
    // Parity waits don't consume state: sub-A (already past phase S-2) and sub-B
    // (never waited barH) both correctly block until phase S-1 completes.
    mbar_wait_acq(barH, (S - 1) & 1);
    cluster_sync_all();
}

// ---------------- launch ------------------------------------------------------
extern "C" void kernel_launch(void* const* d_in, const int* in_sizes, int n_in,
                              void* d_out, int out_size)
{
    const float* x    = (const float*)d_in[0];
    const float* W_r  = (const float*)d_in[1];
    const float* b_r  = (const float*)d_in[2];
    const float* W_z  = (const float*)d_in[3];
    const float* b_z  = (const float*)d_in[4];
    const float* W_h  = (const float*)d_in[5];
    const float* b_h  = (const float*)d_in[6];
    const float* W_fc = (const float*)d_in[7];
    const float* b_fc = (const float*)d_in[8];
    float* out = (float*)d_out;
    float* hlast = out + (size_t)B * S * O;

    float *gx, *hsp, *Wx, *bx;
    cudaGetSymbolAddress((void**)&gx,  g_gx);
    cudaGetSymbolAddress((void**)&hsp, g_hs);
    cudaGetSymbolAddress((void**)&Wx,  g_Wx);
    cudaGetSymbolAddress((void**)&bx,  g_bx);

    pack_weights<<<G3, 64>>>(W_r, W_z, W_h, b_r, b_z, b_h);
    gemm_bias<<<dim3(NROWS / 128, G3 / 64), 256>>>(x, Wx, bx, gx, G3);
    dummy_k<<<1, 32>>>();   // keeps gru_rec on the ncu capture slot
    gru_rec<<<128, 384>>>(gx, W_r, W_z, W_h, hsp, hlast);
    gemm_bias<<<dim3(NROWS / 128, O / 64), 256>>>(hsp, W_fc, b_fc, out, O);
}